// round 14
// baseline (speedup 1.0000x reference)
#include <cuda_runtime.h>
#include <cuda_bf16.h>
#include <cuda_fp16.h>
#include <math.h>
#include <stdint.h>

#define B_    4
#define N_    2048
#define H_    16
#define DH    64
#define DM    1024
#define M_TOT (B_ * N_)        // 8192
#define QKV_N (3 * DM)         // 3072
#define NROWS (B_ * H_ * N_)   // 131072

// ---------------------------------------------------------------------------
// Scratch (static device globals — allocation-free per harness rules)
// ---------------------------------------------------------------------------
__device__ float g_q [(size_t)NROWS * DH];
__device__ float g_k [(size_t)NROWS * DH];

__device__ __half g_qh[(size_t)NROWS * DH];   // normalized q*scale*log2e, fp16 hi
__device__ __half g_ql[(size_t)NROWS * DH];   // fp16 lo
__device__ __half g_kh[(size_t)NROWS * DH];   // normalized k, single fp16
__device__ __half g_vh[(size_t)NROWS * DH];   // v fp16 hi
__device__ __half g_vl[(size_t)NROWS * DH];   // v fp16 lo

__device__ __half g_x_h [(size_t)M_TOT * DM]; // x fp16 hi
__device__ __half g_x_l [(size_t)M_TOT * DM]; // x fp16 lo
__device__ __half g_wq_h[(size_t)QKV_N * DM]; // w_qkv single fp16
__device__ __half g_wo_h[(size_t)DM * DM];    // w_out single fp16
__device__ __half g_aoh [(size_t)M_TOT * DM]; // attention out fp16 hi
__device__ __half g_aol [(size_t)M_TOT * DM]; // attention out fp16 lo

// ---------------------------------------------------------------------------
// Helpers
// ---------------------------------------------------------------------------
__device__ __forceinline__ void mma_fp16(float* c, const uint32_t* a,
                                         uint32_t b0, uint32_t b1) {
    asm volatile(
        "mma.sync.aligned.m16n8k16.row.col.f32.f16.f16.f32 "
        "{%0,%1,%2,%3}, {%4,%5,%6,%7}, {%8,%9}, {%0,%1,%2,%3};\n"
        : "+f"(c[0]), "+f"(c[1]), "+f"(c[2]), "+f"(c[3])
        : "r"(a[0]), "r"(a[1]), "r"(a[2]), "r"(a[3]), "r"(b0), "r"(b1));
}
__device__ __forceinline__ uint32_t pack_f16(float x, float y) {
    __half2 t = __floats2half2_rn(x, y);
    return *(uint32_t*)&t;
}
__device__ __forceinline__ float f16_round(float x) {
    return __half2float(__float2half_rn(x));
}
__device__ __forceinline__ uint32_t smem_u32(const void* p) {
    uint32_t a;
    asm("{ .reg .u64 t; cvta.to.shared.u64 t, %1; cvt.u32.u64 %0, t; }" : "=r"(a) : "l"(p));
    return a;
}
__device__ __forceinline__ void cp16(uint32_t dst, const void* src) {
    asm volatile("cp.async.cg.shared.global [%0], [%1], 16;" :: "r"(dst), "l"(src));
}
#define CP_COMMIT() asm volatile("cp.async.commit_group;" ::: "memory")
#define CP_WAIT0()  asm volatile("cp.async.wait_group 0;" ::: "memory")

__device__ __forceinline__ void ldsm_x4(uint32_t* r, uint32_t addr) {
    asm volatile("ldmatrix.sync.aligned.m8n8.x4.shared.b16 {%0,%1,%2,%3}, [%4];"
                 : "=r"(r[0]), "=r"(r[1]), "=r"(r[2]), "=r"(r[3]) : "r"(addr));
}
__device__ __forceinline__ void ldsm_x4_t(uint32_t* r, uint32_t addr) {
    asm volatile("ldmatrix.sync.aligned.m8n8.x4.trans.shared.b16 {%0,%1,%2,%3}, [%4];"
                 : "=r"(r[0]), "=r"(r[1]), "=r"(r[2]), "=r"(r[3]) : "r"(addr));
}

// ---------------------------------------------------------------------------
// f32 -> (fp16 hi, fp16 lo).  4 elems / thread.
// ---------------------------------------------------------------------------
__global__ __launch_bounds__(256) void decomp_f16_kernel(
    const float* __restrict__ src, __half* __restrict__ hi, __half* __restrict__ lo)
{
    size_t i = ((size_t)blockIdx.x * 256 + threadIdx.x) * 4;
    float4 v = *(const float4*)(src + i);
    *(uint32_t*)(hi + i)     = pack_f16(v.x, v.y);
    *(uint32_t*)(hi + i + 2) = pack_f16(v.z, v.w);
    *(uint32_t*)(lo + i)     = pack_f16(v.x - f16_round(v.x), v.y - f16_round(v.y));
    *(uint32_t*)(lo + i + 2) = pack_f16(v.z - f16_round(v.z), v.w - f16_round(v.w));
}

// f32 -> fp16 (single).  4 elems / thread.
__global__ __launch_bounds__(256) void conv_f16_kernel(
    const float* __restrict__ src, __half* __restrict__ dst)
{
    size_t i = ((size_t)blockIdx.x * 256 + threadIdx.x) * 4;
    float4 v = *(const float4*)(src + i);
    *(uint32_t*)(dst + i)     = pack_f16(v.x, v.y);
    *(uint32_t*)(dst + i + 2) = pack_f16(v.z, v.w);
}

// ---------------------------------------------------------------------------
// fp16 2-pass GEMM:  C = (Ahi + Alo) @ Bh^T,  B single fp16.
// K-chunk 64, 2-stage double buffer, ONE barrier per chunk (attention-style).
// Block 128x128, 256 thr (8 warps 4x2), warp tile 32x64, 2 CTAs/SM.
// Row stride 144 B (128 data + 16 pad; 16-B aligned, conflict-free).
// Per chunk per warp: 32 LDSM / 64 MMA / 1 barrier.
// ---------------------------------------------------------------------------
#define GLDB  144
#define F_ARR   (128 * GLDB)                // 18432 B
#define F_AH 0
#define F_AL (1 * F_ARR)
#define F_BH (2 * F_ARR)
#define F_STAGE (3 * F_ARR)                 // 55296 B
#define FS_TOTAL (2 * F_STAGE)              // 110592 B

__global__ __launch_bounds__(256, 2) void gemm_f16_kernel(
    const __half* __restrict__ Ahi, const __half* __restrict__ Alo,
    const __half* __restrict__ Bh,
    const float* __restrict__ bias, float* __restrict__ Cout, int mode)
{
    extern __shared__ char smem[];
    const uint32_t sb = smem_u32(smem);
    const int tid  = threadIdx.x;
    const int wid  = tid >> 5;
    const int lane = tid & 31;
    const int wm   = wid & 3;
    const int wn   = wid >> 2;
    const int qd   = lane & 3;
    const int r4   = lane >> 2;
    const int m0 = blockIdx.y * 128;
    const int n0 = blockIdx.x * 128;

    const int lrow = ((lane >> 3) & 1) * 8 + (lane & 7);
    const int lcol = (lane >> 4) * 8;       // halfwords

    float c[2][8][4];
#pragma unroll
    for (int mt = 0; mt < 2; mt++)
#pragma unroll
        for (int nt = 0; nt < 8; nt++)
#pragma unroll
            for (int j = 0; j < 4; j++) c[mt][nt][j] = 0.f;

    // loader: 2 threads/row, 64 B each
    const int row  = tid >> 1;              // 0..127
    const int half = tid & 1;
    const size_t gA0 = (size_t)(m0 + row) * DM * 2 + half * 64;   // bytes
    const size_t gB0 = (size_t)(n0 + row) * DM * 2 + half * 64;
    const uint32_t sRow = (uint32_t)(row * GLDB + half * 64);

    auto issue = [&](int ch, int buf) {
        const size_t ko = (size_t)ch * 128;         // 64 fp16 = 128 B
        const uint32_t s = sb + buf * F_STAGE + sRow;
#pragma unroll
        for (int i = 0; i < 4; i++) {
            cp16(s + F_AH + i * 16, (const char*)Ahi + gA0 + ko + i * 16);
            cp16(s + F_AL + i * 16, (const char*)Alo + gA0 + ko + i * 16);
            cp16(s + F_BH + i * 16, (const char*)Bh + gB0 + ko + i * 16);
        }
        CP_COMMIT();
    };

    issue(0, 0);

    for (int ch = 0; ch < 16; ch++) {
        CP_WAIT0();
        __syncthreads();
        const uint32_t sbuf = sb + (ch & 1) * F_STAGE;

#pragma unroll
        for (int ks = 0; ks < 4; ks++) {
            uint32_t ah[2][4], al[2][4];
#pragma unroll
            for (int mt = 0; mt < 2; mt++) {
                const uint32_t abase = sbuf +
                    (uint32_t)((wm * 32 + mt * 16 + lrow) * GLDB + (ks * 16 + lcol) * 2);
                ldsm_x4(ah[mt], abase + F_AH);
                ldsm_x4(al[mt], abase + F_AL);
            }
#pragma unroll
            for (int p = 0; p < 4; p++) {
                const uint32_t bbase = sbuf +
                    (uint32_t)((wn * 64 + p * 16 + lrow) * GLDB + (ks * 16 + lcol) * 2);
                uint32_t bh[4];
                ldsm_x4(bh, bbase + F_BH);
#pragma unroll
                for (int mt = 0; mt < 2; mt++) {
                    mma_fp16(c[mt][2 * p],     ah[mt], bh[0], bh[2]);
                    mma_fp16(c[mt][2 * p + 1], ah[mt], bh[1], bh[3]);
                }
#pragma unroll
                for (int mt = 0; mt < 2; mt++) {
                    mma_fp16(c[mt][2 * p],     al[mt], bh[0], bh[2]);
                    mma_fp16(c[mt][2 * p + 1], al[mt], bh[1], bh[3]);
                }
            }
        }
        // prefetch next chunk into the other buffer (attention-style: its prior
        // readers finished before this iteration's barrier)
        if (ch + 1 < 16) issue(ch + 1, (ch + 1) & 1);
    }

    // ---- epilogue ----
#pragma unroll
    for (int nt = 0; nt < 8; nt++) {
        const int nb = n0 + wn * 64 + nt * 8 + qd * 2;
        if (mode == 0) {
            const int which = nb >> 10;
            const int rem   = nb & 1023;
            const int hh    = rem >> 6;
            const int d     = rem & 63;
            const float b0 = bias[nb], b1 = bias[nb + 1];
#pragma unroll
            for (int mt = 0; mt < 2; mt++) {
#pragma unroll
                for (int rr = 0; rr < 2; rr++) {
                    const int m = m0 + wm * 32 + mt * 16 + r4 + rr * 8;
                    const int bidx = m >> 11, ntok = m & 2047;
                    const size_t sidx = ((size_t)(bidx * H_ + hh) * N_ + ntok) * DH + d;
                    float f0 = c[mt][nt][rr * 2 + 0] + b0;
                    float f1 = c[mt][nt][rr * 2 + 1] + b1;
                    if (which == 0)      *(float2*)(g_q + sidx) = make_float2(f0, f1);
                    else if (which == 1) *(float2*)(g_k + sidx) = make_float2(f0, f1);
                    else {
                        *(uint32_t*)(g_vh + sidx) = pack_f16(f0, f1);
                        *(uint32_t*)(g_vl + sidx) = pack_f16(f0 - f16_round(f0),
                                                             f1 - f16_round(f1));
                    }
                }
            }
        } else {
#pragma unroll
            for (int mt = 0; mt < 2; mt++) {
#pragma unroll
                for (int rr = 0; rr < 2; rr++) {
                    const int m = m0 + wm * 32 + mt * 16 + r4 + rr * 8;
                    *(float2*)(Cout + (size_t)m * DM + nb) =
                        make_float2(c[mt][nt][rr * 2 + 0], c[mt][nt][rr * 2 + 1]);
                }
            }
        }
    }
}

// ---------------------------------------------------------------------------
// L2 normalize + fp16 emit. blockIdx.y 0: q (scale*log2e folded, hi+lo),
// 1: k (single fp16).
// ---------------------------------------------------------------------------
__global__ __launch_bounds__(256) void l2norm_kernel(const float* __restrict__ lscale)
{
    const int which = blockIdx.y;
    const int warp = (blockIdx.x * blockDim.x + threadIdx.x) >> 5;
    const int lane = threadIdx.x & 31;
    if (warp >= NROWS) return;
    const float* row = (which ? g_k : g_q) + (size_t)warp * DH;
    float2 v = *(const float2*)(row + 2 * lane);
    float ss = v.x * v.x + v.y * v.y;
#pragma unroll
    for (int off = 16; off >= 1; off >>= 1)
        ss += __shfl_xor_sync(0xffffffffu, ss, off);
    float sc = 1.f;
    if (which == 0) {
        const int h = (warp >> 11) & (H_ - 1);
        sc = __expf(fminf(lscale[h], 4.6051702f)) * 1.44269504f;   // scale * log2(e)
    }
    const float inv = sc / fmaxf(sqrtf(ss), 1e-12f);
    const float f0 = v.x * inv, f1 = v.y * inv;
    const size_t idx = (size_t)warp * DH + 2 * lane;
    if (which == 0) {
        *(uint32_t*)(g_qh + idx) = pack_f16(f0, f1);
        *(uint32_t*)(g_ql + idx) = pack_f16(f0 - f16_round(f0), f1 - f16_round(f1));
    } else {
        *(uint32_t*)(g_kh + idx) = pack_f16(f0, f1);
    }
}

// ---------------------------------------------------------------------------
// Flash attention, fp16 2-pass mma.sync + ldmatrix, static-max softmax.
// QK: qh*k + ql*k (k single fp16).  PV: p*vh + p*vl.
// CTA = 256 thr (8 warps), Q block 128, K tile 64, KV double-buffered.
// smem: Q 2x18432 + KV 2 stages x 3 x 9216 = 92160 B -> 2 CTAs/SM.
// ---------------------------------------------------------------------------
#define ALDB 144
#define AS_QH 0
#define AS_QL (AS_QH + 128 * ALDB)
#define AS_KV (AS_QL + 128 * ALDB)            // 36864
#define KV_ARR   (64 * ALDB)                  // 9216
#define KV_STAGE (3 * KV_ARR)                 // 27648
#define KV_KH 0
#define KV_VH (1 * KV_ARR)
#define KV_VL (2 * KV_ARR)
#define AS_TOTAL (AS_KV + 2 * KV_STAGE)       // 92160 B

__global__ __launch_bounds__(256, 2) void attn_mma_kernel(const float* __restrict__ lscale)
{
    extern __shared__ char smem[];
    const uint32_t sb = smem_u32(smem);
    const int tid  = threadIdx.x;
    const int wid  = tid >> 5;
    const int lane = tid & 31;
    const int qd   = lane & 3;
    const int r4   = lane >> 2;
    const int lrow = ((lane >> 3) & 1) * 8 + (lane & 7);
    const int lcol = (lane >> 4) * 8;
    const int bh = blockIdx.y;
    const int b  = bh >> 4;
    const int h  = bh & 15;
    const int q0 = blockIdx.x * 128;

    const float cs = __expf(fminf(lscale[h], 4.6051702f)) * 1.44269504f;

    const size_t rowbase = (size_t)bh * N_ * DH;

    // ---- Q tile (cp.async, once): 128 rows, 2 threads/row ----
    {
        const int r = tid >> 1, hf = tid & 1;
        const size_t off = (rowbase + (size_t)(q0 + r) * DH) * 2 + hf * 64;
        const uint32_t sq = sb + (uint32_t)(r * ALDB + hf * 64);
#pragma unroll
        for (int i = 0; i < 4; i++) {
            cp16(sq + AS_QH + i * 16, (const char*)g_qh + off + i * 16);
            cp16(sq + AS_QL + i * 16, (const char*)g_ql + off + i * 16);
        }
    }
    // ---- KV tile issue: 64 rows, 4 threads/row (32 B each), 3 arrays ----
    const int kr = tid >> 2;
    const int kq = (tid & 3) * 32;
    auto issue_kv = [&](int j0, int buf) {
        const size_t off = (rowbase + (size_t)(j0 + kr) * DH) * 2 + kq;
        const uint32_t s = sb + AS_KV + buf * KV_STAGE + (uint32_t)(kr * ALDB + kq);
#pragma unroll
        for (int i = 0; i < 2; i++) {
            cp16(s + KV_KH + i * 16, (const char*)g_kh + off + i * 16);
            cp16(s + KV_VH + i * 16, (const char*)g_vh + off + i * 16);
            cp16(s + KV_VL + i * 16, (const char*)g_vl + off + i * 16);
        }
        CP_COMMIT();
    };
    issue_kv(0, 0);

    float o[8][4];
#pragma unroll
    for (int dn = 0; dn < 8; dn++)
#pragma unroll
        for (int j = 0; j < 4; j++) o[dn][j] = 0.f;
    float lsum0 = 0.f, lsum1 = 0.f;

    for (int t = 0; t < N_ / 64; t++) {
        CP_WAIT0();
        __syncthreads();
        const uint32_t kvb = sb + AS_KV + (t & 1) * KV_STAGE;

        // ---- S = Q K^T (fp16 2-pass) ----
        float s[8][4];
#pragma unroll
        for (int nt = 0; nt < 8; nt++)
#pragma unroll
            for (int j = 0; j < 4; j++) s[nt][j] = 0.f;

#pragma unroll
        for (int ks = 0; ks < 4; ks++) {
            uint32_t aqh[4], aql[4];
            const uint32_t abase = sb +
                (uint32_t)((wid * 16 + lrow) * ALDB + (ks * 16 + lcol) * 2);
            ldsm_x4(aqh, abase + AS_QH);
            ldsm_x4(aql, abase + AS_QL);
#pragma unroll
            for (int p = 0; p < 4; p++) {
                const uint32_t bbase = kvb +
                    (uint32_t)((p * 16 + lrow) * ALDB + (ks * 16 + lcol) * 2);
                uint32_t kh[4];
                ldsm_x4(kh, bbase + KV_KH);
                mma_fp16(s[2 * p],     aqh, kh[0], kh[2]);
                mma_fp16(s[2 * p + 1], aqh, kh[1], kh[3]);
                mma_fp16(s[2 * p],     aql, kh[0], kh[2]);
                mma_fp16(s[2 * p + 1], aql, kh[1], kh[3]);
            }
        }

        // ---- static-shift softmax numerators ----
#pragma unroll
        for (int nt = 0; nt < 8; nt++) {
            s[nt][0] = exp2f(s[nt][0] - cs);
            s[nt][1] = exp2f(s[nt][1] - cs);
            s[nt][2] = exp2f(s[nt][2] - cs);
            s[nt][3] = exp2f(s[nt][3] - cs);
            lsum0 += s[nt][0] + s[nt][1];
            lsum1 += s[nt][2] + s[nt][3];
        }

        // ---- O += P V (fp16 2-pass: p*(vh+vl)) ----
#pragma unroll
        for (int kt = 0; kt < 4; kt++) {
            const int u = 2 * kt, v2 = 2 * kt + 1;
            uint32_t pah[4];
            pah[0] = pack_f16(s[u][0],  s[u][1]);
            pah[1] = pack_f16(s[u][2],  s[u][3]);
            pah[2] = pack_f16(s[v2][0], s[v2][1]);
            pah[3] = pack_f16(s[v2][2], s[v2][3]);
#pragma unroll
            for (int p = 0; p < 4; p++) {
                const uint32_t vbase = kvb +
                    (uint32_t)((kt * 16 + lrow) * ALDB + (p * 16 + lcol) * 2);
                uint32_t vh[4], vl[4];
                ldsm_x4_t(vh, vbase + KV_VH);
                ldsm_x4_t(vl, vbase + KV_VL);
                mma_fp16(o[2 * p],     pah, vh[0], vh[1]);
                mma_fp16(o[2 * p + 1], pah, vh[2], vh[3]);
                mma_fp16(o[2 * p],     pah, vl[0], vl[1]);
                mma_fp16(o[2 * p + 1], pah, vl[2], vl[3]);
            }
        }
        if (t + 1 < N_ / 64) issue_kv((t + 1) * 64, (t + 1) & 1);
    }

    // ---- final row-sum reduction across the quad, then normalize ----
    lsum0 += __shfl_xor_sync(0xffffffffu, lsum0, 1);
    lsum0 += __shfl_xor_sync(0xffffffffu, lsum0, 2);
    lsum1 += __shfl_xor_sync(0xffffffffu, lsum1, 1);
    lsum1 += __shfl_xor_sync(0xffffffffu, lsum1, 2);
    const float inv0 = 1.f / lsum0;
    const float inv1 = 1.f / lsum1;
#pragma unroll
    for (int dn = 0; dn < 8; dn++) {
        const int d = dn * 8 + qd * 2;
#pragma unroll
        for (int rr = 0; rr < 2; rr++) {
            const int n = q0 + wid * 16 + r4 + rr * 8;
            const float inv = rr ? inv1 : inv0;
            const float f0 = o[dn][rr * 2 + 0] * inv;
            const float f1 = o[dn][rr * 2 + 1] * inv;
            const size_t idx = (size_t)(b * N_ + n) * DM + h * 64 + d;
            *(uint32_t*)(g_aoh + idx) = pack_f16(f0, f1);
            *(uint32_t*)(g_aol + idx) = pack_f16(f0 - f16_round(f0), f1 - f16_round(f1));
        }
    }
}

// ---------------------------------------------------------------------------
extern "C" void kernel_launch(void* const* d_in, const int* in_sizes, int n_in,
                              void* d_out, int out_size)
{
    const float* x      = (const float*)d_in[0];
    const float* w_qkv  = (const float*)d_in[1];
    const float* b_qkv  = (const float*)d_in[2];
    const float* w_out  = (const float*)d_in[3];
    const float* lscale = (const float*)d_in[4];
    float* out = (float*)d_out;

    __half *xh, *xl, *wqh, *woh, *aoh, *aol;
    cudaGetSymbolAddress((void**)&xh,  g_x_h);
    cudaGetSymbolAddress((void**)&xl,  g_x_l);
    cudaGetSymbolAddress((void**)&wqh, g_wq_h);
    cudaGetSymbolAddress((void**)&woh, g_wo_h);
    cudaGetSymbolAddress((void**)&aoh, g_aoh);
    cudaGetSymbolAddress((void**)&aol, g_aol);

    cudaFuncSetAttribute(gemm_f16_kernel, cudaFuncAttributeMaxDynamicSharedMemorySize, FS_TOTAL);
    cudaFuncSetAttribute(attn_mma_kernel, cudaFuncAttributeMaxDynamicSharedMemorySize, AS_TOTAL);

    // 0. convert inputs
    decomp_f16_kernel<<<(M_TOT * DM) / 1024, 256>>>(x, xh, xl);
    conv_f16_kernel<<<(QKV_N * DM) / 1024, 256>>>(w_qkv, wqh);
    conv_f16_kernel<<<(DM * DM)    / 1024, 256>>>(w_out, woh);

    // 1. QKV projection (fp16 2-pass): q,k -> float; v -> fp16 hi/lo
    dim3 g1(QKV_N / 128, M_TOT / 128);     // (24, 64)
    gemm_f16_kernel<<<g1, 256, FS_TOTAL>>>(xh, xl, wqh, b_qkv, nullptr, 0);

    // 2. normalize q (scale*log2e folded, fp16 hi/lo) and k (single fp16)
    dim3 g2(NROWS / 8, 2);
    l2norm_kernel<<<g2, 256>>>(lscale);

    // 3. flash attention (fp16 2-pass) -> ao fp16 hi/lo
    dim3 g3(N_ / 128, B_ * H_);            // (16, 64)
    attn_mma_kernel<<<g3, 256, AS_TOTAL>>>(lscale);

    // 4. output projection (fp16 2-pass) -> d_out
    dim3 g4(DM / 128, M_TOT / 128);        // (8, 64)
    gemm_f16_kernel<<<g4, 256, FS_TOTAL>>>(aoh, aol, woh, nullptr, out, 1);
}

// round 15
// speedup vs baseline: 1.0678x; 1.0678x over previous
#include <cuda_runtime.h>
#include <cuda_bf16.h>
#include <cuda_fp16.h>
#include <math.h>
#include <stdint.h>

#define B_    4
#define N_    2048
#define H_    16
#define DH    64
#define DM    1024
#define M_TOT (B_ * N_)        // 8192
#define QKV_N (3 * DM)         // 3072
#define NROWS (B_ * H_ * N_)   // 131072

// ---------------------------------------------------------------------------
// Scratch (static device globals — allocation-free per harness rules)
// ---------------------------------------------------------------------------
__device__ __half g_qh[(size_t)NROWS * DH];   // normalized q*scale*log2e, fp16 hi
__device__ __half g_ql[(size_t)NROWS * DH];   // fp16 lo
__device__ __half g_kh[(size_t)NROWS * DH];   // normalized k, single fp16
__device__ __half g_vh[(size_t)NROWS * DH];   // v fp16 hi
__device__ __half g_vl[(size_t)NROWS * DH];   // v fp16 lo

__device__ __half g_x_h [(size_t)M_TOT * DM]; // x fp16 hi
__device__ __half g_x_l [(size_t)M_TOT * DM]; // x fp16 lo
__device__ __half g_wq_h[(size_t)QKV_N * DM]; // w_qkv single fp16
__device__ __half g_wo_h[(size_t)DM * DM];    // w_out single fp16
__device__ __half g_aoh [(size_t)M_TOT * DM]; // attention out fp16 hi
__device__ __half g_aol [(size_t)M_TOT * DM]; // attention out fp16 lo

// ---------------------------------------------------------------------------
// Helpers
// ---------------------------------------------------------------------------
__device__ __forceinline__ void mma_fp16(float* c, const uint32_t* a,
                                         uint32_t b0, uint32_t b1) {
    asm volatile(
        "mma.sync.aligned.m16n8k16.row.col.f32.f16.f16.f32 "
        "{%0,%1,%2,%3}, {%4,%5,%6,%7}, {%8,%9}, {%0,%1,%2,%3};\n"
        : "+f"(c[0]), "+f"(c[1]), "+f"(c[2]), "+f"(c[3])
        : "r"(a[0]), "r"(a[1]), "r"(a[2]), "r"(a[3]), "r"(b0), "r"(b1));
}
__device__ __forceinline__ uint32_t pack_f16(float x, float y) {
    __half2 t = __floats2half2_rn(x, y);
    return *(uint32_t*)&t;
}
__device__ __forceinline__ float f16_round(float x) {
    return __half2float(__float2half_rn(x));
}
__device__ __forceinline__ uint32_t smem_u32(const void* p) {
    uint32_t a;
    asm("{ .reg .u64 t; cvta.to.shared.u64 t, %1; cvt.u32.u64 %0, t; }" : "=r"(a) : "l"(p));
    return a;
}
__device__ __forceinline__ void cp16(uint32_t dst, const void* src) {
    asm volatile("cp.async.cg.shared.global [%0], [%1], 16;" :: "r"(dst), "l"(src));
}
#define CP_COMMIT() asm volatile("cp.async.commit_group;" ::: "memory")
#define CP_WAIT0()  asm volatile("cp.async.wait_group 0;" ::: "memory")
#define CP_WAIT2()  asm volatile("cp.async.wait_group 2;" ::: "memory")

__device__ __forceinline__ void ldsm_x4(uint32_t* r, uint32_t addr) {
    asm volatile("ldmatrix.sync.aligned.m8n8.x4.shared.b16 {%0,%1,%2,%3}, [%4];"
                 : "=r"(r[0]), "=r"(r[1]), "=r"(r[2]), "=r"(r[3]) : "r"(addr));
}
__device__ __forceinline__ void ldsm_x4_t(uint32_t* r, uint32_t addr) {
    asm volatile("ldmatrix.sync.aligned.m8n8.x4.trans.shared.b16 {%0,%1,%2,%3}, [%4];"
                 : "=r"(r[0]), "=r"(r[1]), "=r"(r[2]), "=r"(r[3]) : "r"(addr));
}

// ---------------------------------------------------------------------------
// f32 -> (fp16 hi, fp16 lo).  4 elems / thread.
// ---------------------------------------------------------------------------
__global__ __launch_bounds__(256) void decomp_f16_kernel(
    const float* __restrict__ src, __half* __restrict__ hi, __half* __restrict__ lo)
{
    size_t i = ((size_t)blockIdx.x * 256 + threadIdx.x) * 4;
    float4 v = *(const float4*)(src + i);
    *(uint32_t*)(hi + i)     = pack_f16(v.x, v.y);
    *(uint32_t*)(hi + i + 2) = pack_f16(v.z, v.w);
    *(uint32_t*)(lo + i)     = pack_f16(v.x - f16_round(v.x), v.y - f16_round(v.y));
    *(uint32_t*)(lo + i + 2) = pack_f16(v.z - f16_round(v.z), v.w - f16_round(v.w));
}

// f32 -> fp16 (single).  4 elems / thread.
__global__ __launch_bounds__(256) void conv_f16_kernel(
    const float* __restrict__ src, __half* __restrict__ dst)
{
    size_t i = ((size_t)blockIdx.x * 256 + threadIdx.x) * 4;
    float4 v = *(const float4*)(src + i);
    *(uint32_t*)(dst + i)     = pack_f16(v.x, v.y);
    *(uint32_t*)(dst + i + 2) = pack_f16(v.z, v.w);
}

// ---------------------------------------------------------------------------
// fp16 2-pass GEMM (R13 mainloop):  C = (Ahi + Alo) @ Bh^T,  B single fp16.
// 4-stage cp.async pipeline, K-chunk 16, ldmatrix frags.
// Block 128x128, 256 thr (8 warps 4x2), warp tile 32x64, 2 CTAs/SM.
// mode 0 (QKV): bias + FUSED L2-NORM epilogue:
//   each warp's 64-col n-block == one head's Dh; q/k rows normalized
//   in-register (quad shuffles) and emitted fp16 (q hi/lo w/ scale, k single);
//   v emitted fp16 hi/lo.  No f32 round-trip, no separate l2norm kernel.
// mode 1: row-major float store to Cout.
// ---------------------------------------------------------------------------
#define GLDB  48
#define F_ARR   (128 * GLDB)                // 6144 B
#define F_AH 0
#define F_AL (1 * F_ARR)
#define F_BH (2 * F_ARR)
#define F_STAGE (3 * F_ARR)                 // 18432 B
#define FS_TOTAL (4 * F_STAGE)              // 73728 B

__global__ __launch_bounds__(256, 2) void gemm_f16_kernel(
    const __half* __restrict__ Ahi, const __half* __restrict__ Alo,
    const __half* __restrict__ Bh,
    const float* __restrict__ bias, const float* __restrict__ lscale,
    float* __restrict__ Cout, int mode)
{
    extern __shared__ char smem[];
    const uint32_t sb = smem_u32(smem);
    const int tid  = threadIdx.x;
    const int wid  = tid >> 5;
    const int lane = tid & 31;
    const int wm   = wid & 3;
    const int wn   = wid >> 2;
    const int qd   = lane & 3;
    const int r4   = lane >> 2;
    const int m0 = blockIdx.y * 128;
    const int n0 = blockIdx.x * 128;

    const int lrow = ((lane >> 3) & 1) * 8 + (lane & 7);
    const int lcol = (lane >> 4) * 8;

    float c[2][8][4];
#pragma unroll
    for (int mt = 0; mt < 2; mt++)
#pragma unroll
        for (int nt = 0; nt < 8; nt++)
#pragma unroll
            for (int j = 0; j < 4; j++) c[mt][nt][j] = 0.f;

    const int row  = tid >> 1;
    const int half = tid & 1;
    const size_t gA0 = (size_t)(m0 + row) * DM * 2 + half * 16;
    const size_t gB0 = (size_t)(n0 + row) * DM * 2 + half * 16;
    const uint32_t sRow = (uint32_t)(row * GLDB + half * 16);

    auto issue = [&](int ch) {
        const size_t ko = (size_t)ch * 32;
        const uint32_t s = sb + (ch & 3) * F_STAGE + sRow;
        cp16(s + F_AH, (const char*)Ahi + gA0 + ko);
        cp16(s + F_AL, (const char*)Alo + gA0 + ko);
        cp16(s + F_BH, (const char*)Bh + gB0 + ko);
        CP_COMMIT();
    };

    issue(0); issue(1); issue(2);

    for (int ch = 0; ch < 64; ch++) {
        CP_WAIT2();
        __syncthreads();

        const uint32_t sbuf = sb + (ch & 3) * F_STAGE;
        uint32_t ah[2][4], al[2][4];
#pragma unroll
        for (int mt = 0; mt < 2; mt++) {
            const uint32_t abase = sbuf +
                (uint32_t)((wm * 32 + mt * 16 + lrow) * GLDB + lcol * 2);
            ldsm_x4(ah[mt], abase + F_AH);
            ldsm_x4(al[mt], abase + F_AL);
        }
#pragma unroll
        for (int p = 0; p < 4; p++) {
            const uint32_t bbase = sbuf +
                (uint32_t)((wn * 64 + p * 16 + lrow) * GLDB + lcol * 2);
            uint32_t bh[4];
            ldsm_x4(bh, bbase + F_BH);
#pragma unroll
            for (int mt = 0; mt < 2; mt++) {
                mma_fp16(c[mt][2 * p],     ah[mt], bh[0], bh[2]);
                mma_fp16(c[mt][2 * p + 1], ah[mt], bh[1], bh[3]);
            }
#pragma unroll
            for (int mt = 0; mt < 2; mt++) {
                mma_fp16(c[mt][2 * p],     al[mt], bh[0], bh[2]);
                mma_fp16(c[mt][2 * p + 1], al[mt], bh[1], bh[3]);
            }
        }
        if (ch + 3 < 64) issue(ch + 3);
    }

    // ---- epilogue ----
    if (mode == 1) {
#pragma unroll
        for (int nt = 0; nt < 8; nt++) {
            const int nb = n0 + wn * 64 + nt * 8 + qd * 2;
#pragma unroll
            for (int mt = 0; mt < 2; mt++) {
#pragma unroll
                for (int rr = 0; rr < 2; rr++) {
                    const int m = m0 + wm * 32 + mt * 16 + r4 + rr * 8;
                    *(float2*)(Cout + (size_t)m * DM + nb) =
                        make_float2(c[mt][nt][rr * 2 + 0], c[mt][nt][rr * 2 + 1]);
                }
            }
        }
        return;
    }

    // mode 0: warp n-block = cols [n0+wn*64, +64) — exactly one head region
    const int nbase = n0 + wn * 64;
    const int which = nbase >> 10;          // 0=q, 1=k, 2=v (warp-uniform)
    const int hh    = (nbase & 1023) >> 6;  // head (warp-uniform)

    // bias for this thread's 16 columns
    float bia[8][2];
#pragma unroll
    for (int nt = 0; nt < 8; nt++) {
        bia[nt][0] = bias[nbase + nt * 8 + qd * 2];
        bia[nt][1] = bias[nbase + nt * 8 + qd * 2 + 1];
    }

    if (which == 2) {
        // v: emit fp16 hi/lo
#pragma unroll
        for (int mt = 0; mt < 2; mt++) {
#pragma unroll
            for (int rr = 0; rr < 2; rr++) {
                const int m = m0 + wm * 32 + mt * 16 + r4 + rr * 8;
                const int bidx = m >> 11, ntok = m & 2047;
                const size_t rbase = ((size_t)(bidx * H_ + hh) * N_ + ntok) * DH;
#pragma unroll
                for (int nt = 0; nt < 8; nt++) {
                    const int d = nt * 8 + qd * 2;
                    float f0 = c[mt][nt][rr * 2 + 0] + bia[nt][0];
                    float f1 = c[mt][nt][rr * 2 + 1] + bia[nt][1];
                    *(uint32_t*)(g_vh + rbase + d) = pack_f16(f0, f1);
                    *(uint32_t*)(g_vl + rbase + d) = pack_f16(f0 - f16_round(f0),
                                                              f1 - f16_round(f1));
                }
            }
        }
    } else {
        // q or k: fused L2 normalization over the head's 64 cols
        float sc_ = 1.f;
        if (which == 0)
            sc_ = __expf(fminf(lscale[hh], 4.6051702f)) * 1.44269504f;
#pragma unroll
        for (int mt = 0; mt < 2; mt++) {
#pragma unroll
            for (int rr = 0; rr < 2; rr++) {
                const int m = m0 + wm * 32 + mt * 16 + r4 + rr * 8;
                const int bidx = m >> 11, ntok = m & 2047;
                const size_t rbase = ((size_t)(bidx * H_ + hh) * N_ + ntok) * DH;
                // local sum of squares over this thread's 16 cols
                float ss = 0.f;
#pragma unroll
                for (int nt = 0; nt < 8; nt++) {
                    float f0 = c[mt][nt][rr * 2 + 0] + bia[nt][0];
                    float f1 = c[mt][nt][rr * 2 + 1] + bia[nt][1];
                    ss += f0 * f0 + f1 * f1;
                }
                // reduce across the quad (qd = lane&3: xor 1, 2)
                ss += __shfl_xor_sync(0xffffffffu, ss, 1);
                ss += __shfl_xor_sync(0xffffffffu, ss, 2);
                const float inv = sc_ / fmaxf(sqrtf(ss), 1e-12f);
#pragma unroll
                for (int nt = 0; nt < 8; nt++) {
                    const int d = nt * 8 + qd * 2;
                    float f0 = (c[mt][nt][rr * 2 + 0] + bia[nt][0]) * inv;
                    float f1 = (c[mt][nt][rr * 2 + 1] + bia[nt][1]) * inv;
                    if (which == 0) {
                        *(uint32_t*)(g_qh + rbase + d) = pack_f16(f0, f1);
                        *(uint32_t*)(g_ql + rbase + d) = pack_f16(f0 - f16_round(f0),
                                                                  f1 - f16_round(f1));
                    } else {
                        *(uint32_t*)(g_kh + rbase + d) = pack_f16(f0, f1);
                    }
                }
            }
        }
    }
}

// ---------------------------------------------------------------------------
// Flash attention, fp16 2-pass mma.sync + ldmatrix, static-max softmax (R13).
// QK: qh*k + ql*k (k single fp16).  PV: p*vh + p*vl.
// CTA = 256 thr (8 warps), Q block 128, K tile 64, KV double-buffered.
// smem: Q 2x18432 + KV 2 stages x 3 x 9216 = 92160 B -> 2 CTAs/SM.
// ---------------------------------------------------------------------------
#define ALDB 144
#define AS_QH 0
#define AS_QL (AS_QH + 128 * ALDB)
#define AS_KV (AS_QL + 128 * ALDB)            // 36864
#define KV_ARR   (64 * ALDB)                  // 9216
#define KV_STAGE (3 * KV_ARR)                 // 27648
#define KV_KH 0
#define KV_VH (1 * KV_ARR)
#define KV_VL (2 * KV_ARR)
#define AS_TOTAL (AS_KV + 2 * KV_STAGE)       // 92160 B

__global__ __launch_bounds__(256, 2) void attn_mma_kernel(const float* __restrict__ lscale)
{
    extern __shared__ char smem[];
    const uint32_t sb = smem_u32(smem);
    const int tid  = threadIdx.x;
    const int wid  = tid >> 5;
    const int lane = tid & 31;
    const int qd   = lane & 3;
    const int r4   = lane >> 2;
    const int lrow = ((lane >> 3) & 1) * 8 + (lane & 7);
    const int lcol = (lane >> 4) * 8;
    const int bh = blockIdx.y;
    const int b  = bh >> 4;
    const int h  = bh & 15;
    const int q0 = blockIdx.x * 128;

    const float cs = __expf(fminf(lscale[h], 4.6051702f)) * 1.44269504f;

    const size_t rowbase = (size_t)bh * N_ * DH;

    // ---- Q tile (cp.async, once): 128 rows, 2 threads/row ----
    {
        const int r = tid >> 1, hf = tid & 1;
        const size_t off = (rowbase + (size_t)(q0 + r) * DH) * 2 + hf * 64;
        const uint32_t sq = sb + (uint32_t)(r * ALDB + hf * 64);
#pragma unroll
        for (int i = 0; i < 4; i++) {
            cp16(sq + AS_QH + i * 16, (const char*)g_qh + off + i * 16);
            cp16(sq + AS_QL + i * 16, (const char*)g_ql + off + i * 16);
        }
    }
    // ---- KV tile issue: 64 rows, 4 threads/row (32 B each), 3 arrays ----
    const int kr = tid >> 2;
    const int kq = (tid & 3) * 32;
    auto issue_kv = [&](int j0, int buf) {
        const size_t off = (rowbase + (size_t)(j0 + kr) * DH) * 2 + kq;
        const uint32_t s = sb + AS_KV + buf * KV_STAGE + (uint32_t)(kr * ALDB + kq);
#pragma unroll
        for (int i = 0; i < 2; i++) {
            cp16(s + KV_KH + i * 16, (const char*)g_kh + off + i * 16);
            cp16(s + KV_VH + i * 16, (const char*)g_vh + off + i * 16);
            cp16(s + KV_VL + i * 16, (const char*)g_vl + off + i * 16);
        }
        CP_COMMIT();
    };
    issue_kv(0, 0);

    float o[8][4];
#pragma unroll
    for (int dn = 0; dn < 8; dn++)
#pragma unroll
        for (int j = 0; j < 4; j++) o[dn][j] = 0.f;
    float lsum0 = 0.f, lsum1 = 0.f;

    for (int t = 0; t < N_ / 64; t++) {
        CP_WAIT0();
        __syncthreads();
        const uint32_t kvb = sb + AS_KV + (t & 1) * KV_STAGE;

        // ---- S = Q K^T (fp16 2-pass) ----
        float s[8][4];
#pragma unroll
        for (int nt = 0; nt < 8; nt++)
#pragma unroll
            for (int j = 0; j < 4; j++) s[nt][j] = 0.f;

#pragma unroll
        for (int ks = 0; ks < 4; ks++) {
            uint32_t aqh[4], aql[4];
            const uint32_t abase = sb +
                (uint32_t)((wid * 16 + lrow) * ALDB + (ks * 16 + lcol) * 2);
            ldsm_x4(aqh, abase + AS_QH);
            ldsm_x4(aql, abase + AS_QL);
#pragma unroll
            for (int p = 0; p < 4; p++) {
                const uint32_t bbase = kvb +
                    (uint32_t)((p * 16 + lrow) * ALDB + (ks * 16 + lcol) * 2);
                uint32_t kh[4];
                ldsm_x4(kh, bbase + KV_KH);
                mma_fp16(s[2 * p],     aqh, kh[0], kh[2]);
                mma_fp16(s[2 * p + 1], aqh, kh[1], kh[3]);
                mma_fp16(s[2 * p],     aql, kh[0], kh[2]);
                mma_fp16(s[2 * p + 1], aql, kh[1], kh[3]);
            }
        }

        // ---- static-shift softmax numerators ----
#pragma unroll
        for (int nt = 0; nt < 8; nt++) {
            s[nt][0] = exp2f(s[nt][0] - cs);
            s[nt][1] = exp2f(s[nt][1] - cs);
            s[nt][2] = exp2f(s[nt][2] - cs);
            s[nt][3] = exp2f(s[nt][3] - cs);
            lsum0 += s[nt][0] + s[nt][1];
            lsum1 += s[nt][2] + s[nt][3];
        }

        // ---- O += P V (fp16 2-pass: p*(vh+vl)) ----
#pragma unroll
        for (int kt = 0; kt < 4; kt++) {
            const int u = 2 * kt, v2 = 2 * kt + 1;
            uint32_t pah[4];
            pah[0] = pack_f16(s[u][0],  s[u][1]);
            pah[1] = pack_f16(s[u][2],  s[u][3]);
            pah[2] = pack_f16(s[v2][0], s[v2][1]);
            pah[3] = pack_f16(s[v2][2], s[v2][3]);
#pragma unroll
            for (int p = 0; p < 4; p++) {
                const uint32_t vbase = kvb +
                    (uint32_t)((kt * 16 + lrow) * ALDB + (p * 16 + lcol) * 2);
                uint32_t vh[4], vl[4];
                ldsm_x4_t(vh, vbase + KV_VH);
                ldsm_x4_t(vl, vbase + KV_VL);
                mma_fp16(o[2 * p],     pah, vh[0], vh[1]);
                mma_fp16(o[2 * p + 1], pah, vh[2], vh[3]);
                mma_fp16(o[2 * p],     pah, vl[0], vl[1]);
                mma_fp16(o[2 * p + 1], pah, vl[2], vl[3]);
            }
        }
        if (t + 1 < N_ / 64) issue_kv((t + 1) * 64, (t + 1) & 1);
    }

    // ---- final row-sum reduction across the quad, then normalize ----
    lsum0 += __shfl_xor_sync(0xffffffffu, lsum0, 1);
    lsum0 += __shfl_xor_sync(0xffffffffu, lsum0, 2);
    lsum1 += __shfl_xor_sync(0xffffffffu, lsum1, 1);
    lsum1 += __shfl_xor_sync(0xffffffffu, lsum1, 2);
    const float inv0 = 1.f / lsum0;
    const float inv1 = 1.f / lsum1;
#pragma unroll
    for (int dn = 0; dn < 8; dn++) {
        const int d = dn * 8 + qd * 2;
#pragma unroll
        for (int rr = 0; rr < 2; rr++) {
            const int n = q0 + wid * 16 + r4 + rr * 8;
            const float inv = rr ? inv1 : inv0;
            const float f0 = o[dn][rr * 2 + 0] * inv;
            const float f1 = o[dn][rr * 2 + 1] * inv;
            const size_t idx = (size_t)(b * N_ + n) * DM + h * 64 + d;
            *(uint32_t*)(g_aoh + idx) = pack_f16(f0, f1);
            *(uint32_t*)(g_aol + idx) = pack_f16(f0 - f16_round(f0), f1 - f16_round(f1));
        }
    }
}

// ---------------------------------------------------------------------------
extern "C" void kernel_launch(void* const* d_in, const int* in_sizes, int n_in,
                              void* d_out, int out_size)
{
    const float* x      = (const float*)d_in[0];
    const float* w_qkv  = (const float*)d_in[1];
    const float* b_qkv  = (const float*)d_in[2];
    const float* w_out  = (const float*)d_in[3];
    const float* lscale = (const float*)d_in[4];
    float* out = (float*)d_out;

    __half *xh, *xl, *wqh, *woh, *aoh, *aol;
    cudaGetSymbolAddress((void**)&xh,  g_x_h);
    cudaGetSymbolAddress((void**)&xl,  g_x_l);
    cudaGetSymbolAddress((void**)&wqh, g_wq_h);
    cudaGetSymbolAddress((void**)&woh, g_wo_h);
    cudaGetSymbolAddress((void**)&aoh, g_aoh);
    cudaGetSymbolAddress((void**)&aol, g_aol);

    cudaFuncSetAttribute(gemm_f16_kernel, cudaFuncAttributeMaxDynamicSharedMemorySize, FS_TOTAL);
    cudaFuncSetAttribute(attn_mma_kernel, cudaFuncAttributeMaxDynamicSharedMemorySize, AS_TOTAL);

    // 0. convert inputs
    decomp_f16_kernel<<<(M_TOT * DM) / 1024, 256>>>(x, xh, xl);
    conv_f16_kernel<<<(QKV_N * DM) / 1024, 256>>>(w_qkv, wqh);
    conv_f16_kernel<<<(DM * DM)    / 1024, 256>>>(w_out, woh);

    // 1. QKV projection (fp16 2-pass) with FUSED bias+l2norm epilogue:
    //    q -> fp16 hi/lo (scaled), k -> fp16, v -> fp16 hi/lo
    dim3 g1(QKV_N / 128, M_TOT / 128);     // (24, 64)
    gemm_f16_kernel<<<g1, 256, FS_TOTAL>>>(xh, xl, wqh, b_qkv, lscale, nullptr, 0);

    // 2. flash attention (fp16 2-pass) -> ao fp16 hi/lo
    dim3 g3(N_ / 128, B_ * H_);            // (16, 64)
    attn_mma_kernel<<<g3, 256, AS_TOTAL>>>(lscale);

    // 3. output projection (fp16 2-pass) -> d_out
    dim3 g4(DM / 128, M_TOT / 128);        // (8, 64)
    gemm_f16_kernel<<<g4, 256, FS_TOTAL>>>(aoh, aol, woh, nullptr, nullptr, out, 1);
}

// round 16
// speedup vs baseline: 1.1477x; 1.0748x over previous
#include <cuda_runtime.h>
#include <cuda_bf16.h>
#include <cuda_fp16.h>
#include <math.h>
#include <stdint.h>

#define B_    4
#define N_    2048
#define H_    16
#define DH    64
#define DM    1024
#define M_TOT (B_ * N_)        // 8192
#define QKV_N (3 * DM)         // 3072
#define NROWS (B_ * H_ * N_)   // 131072

// ---------------------------------------------------------------------------
// Scratch (static device globals — allocation-free per harness rules)
// ---------------------------------------------------------------------------
__device__ __half g_qh[(size_t)NROWS * DH];   // normalized q*scale*log2e, fp16 hi
__device__ __half g_ql[(size_t)NROWS * DH];   // fp16 lo
__device__ __half g_kh[(size_t)NROWS * DH];   // normalized k, single fp16
__device__ __half g_vh[(size_t)NROWS * DH];   // v fp16 hi
__device__ __half g_vl[(size_t)NROWS * DH];   // v fp16 lo

__device__ __half g_x_h [(size_t)M_TOT * DM]; // x fp16 hi
__device__ __half g_x_l [(size_t)M_TOT * DM]; // x fp16 lo
__device__ __half g_wq_h[(size_t)QKV_N * DM]; // w_qkv single fp16
__device__ __half g_wo_h[(size_t)DM * DM];    // w_out single fp16
__device__ __half g_aoh [(size_t)M_TOT * DM]; // attention out fp16 hi
__device__ __half g_aol [(size_t)M_TOT * DM]; // attention out fp16 lo

// ---------------------------------------------------------------------------
// Helpers
// ---------------------------------------------------------------------------
__device__ __forceinline__ void mma_fp16(float* c, const uint32_t* a,
                                         uint32_t b0, uint32_t b1) {
    asm volatile(
        "mma.sync.aligned.m16n8k16.row.col.f32.f16.f16.f32 "
        "{%0,%1,%2,%3}, {%4,%5,%6,%7}, {%8,%9}, {%0,%1,%2,%3};\n"
        : "+f"(c[0]), "+f"(c[1]), "+f"(c[2]), "+f"(c[3])
        : "r"(a[0]), "r"(a[1]), "r"(a[2]), "r"(a[3]), "r"(b0), "r"(b1));
}
__device__ __forceinline__ uint32_t pack_f16(float x, float y) {
    __half2 t = __floats2half2_rn(x, y);
    return *(uint32_t*)&t;
}
__device__ __forceinline__ float f16_round(float x) {
    return __half2float(__float2half_rn(x));
}
__device__ __forceinline__ uint32_t smem_u32(const void* p) {
    uint32_t a;
    asm("{ .reg .u64 t; cvta.to.shared.u64 t, %1; cvt.u32.u64 %0, t; }" : "=r"(a) : "l"(p));
    return a;
}
__device__ __forceinline__ void cp16(uint32_t dst, const void* src) {
    asm volatile("cp.async.cg.shared.global [%0], [%1], 16;" :: "r"(dst), "l"(src));
}
#define CP_COMMIT() asm volatile("cp.async.commit_group;" ::: "memory")
#define CP_WAIT0()  asm volatile("cp.async.wait_group 0;" ::: "memory")
#define CP_WAIT2()  asm volatile("cp.async.wait_group 2;" ::: "memory")

__device__ __forceinline__ void ldsm_x4(uint32_t* r, uint32_t addr) {
    asm volatile("ldmatrix.sync.aligned.m8n8.x4.shared.b16 {%0,%1,%2,%3}, [%4];"
                 : "=r"(r[0]), "=r"(r[1]), "=r"(r[2]), "=r"(r[3]) : "r"(addr));
}
__device__ __forceinline__ void ldsm_x4_t(uint32_t* r, uint32_t addr) {
    asm volatile("ldmatrix.sync.aligned.m8n8.x4.trans.shared.b16 {%0,%1,%2,%3}, [%4];"
                 : "=r"(r[0]), "=r"(r[1]), "=r"(r[2]), "=r"(r[3]) : "r"(addr));
}

// ---------------------------------------------------------------------------
// f32 -> (fp16 hi, fp16 lo).  4 elems / thread.
// ---------------------------------------------------------------------------
__global__ __launch_bounds__(256) void decomp_f16_kernel(
    const float* __restrict__ src, __half* __restrict__ hi, __half* __restrict__ lo)
{
    size_t i = ((size_t)blockIdx.x * 256 + threadIdx.x) * 4;
    float4 v = *(const float4*)(src + i);
    *(uint32_t*)(hi + i)     = pack_f16(v.x, v.y);
    *(uint32_t*)(hi + i + 2) = pack_f16(v.z, v.w);
    *(uint32_t*)(lo + i)     = pack_f16(v.x - f16_round(v.x), v.y - f16_round(v.y));
    *(uint32_t*)(lo + i + 2) = pack_f16(v.z - f16_round(v.z), v.w - f16_round(v.w));
}

// f32 -> fp16 (single).  4 elems / thread.
__global__ __launch_bounds__(256) void conv_f16_kernel(
    const float* __restrict__ src, __half* __restrict__ dst)
{
    size_t i = ((size_t)blockIdx.x * 256 + threadIdx.x) * 4;
    float4 v = *(const float4*)(src + i);
    *(uint32_t*)(dst + i)     = pack_f16(v.x, v.y);
    *(uint32_t*)(dst + i + 2) = pack_f16(v.z, v.w);
}

// ---------------------------------------------------------------------------
// fp16 2-pass GEMM:  C = (Ahi + Alo) @ Bh^T,  B single fp16.
// 4-stage cp.async pipeline, K-chunk 16, ldmatrix frags.
// Block 128x128, 256 thr (8 warps 4x2), warp tile 32x64, 2 CTAs/SM.
// mode 0 (QKV): fused bias+l2norm epilogue; k-head warps SKIP the Alo pass
//   (k is rounded to single fp16 anyway — correction pass wasted there).
// mode 1: row-major float store to Cout.
// ---------------------------------------------------------------------------
#define GLDB  48
#define F_ARR   (128 * GLDB)                // 6144 B
#define F_AH 0
#define F_AL (1 * F_ARR)
#define F_BH (2 * F_ARR)
#define F_STAGE (3 * F_ARR)                 // 18432 B
#define FS_TOTAL (4 * F_STAGE)              // 73728 B

__global__ __launch_bounds__(256, 2) void gemm_f16_kernel(
    const __half* __restrict__ Ahi, const __half* __restrict__ Alo,
    const __half* __restrict__ Bh,
    const float* __restrict__ bias, const float* __restrict__ lscale,
    float* __restrict__ Cout, int mode)
{
    extern __shared__ char smem[];
    const uint32_t sb = smem_u32(smem);
    const int tid  = threadIdx.x;
    const int wid  = tid >> 5;
    const int lane = tid & 31;
    const int wm   = wid & 3;
    const int wn   = wid >> 2;
    const int qd   = lane & 3;
    const int r4   = lane >> 2;
    const int m0 = blockIdx.y * 128;
    const int n0 = blockIdx.x * 128;

    const int lrow = ((lane >> 3) & 1) * 8 + (lane & 7);
    const int lcol = (lane >> 4) * 8;

    // warp-uniform output class for mode 0 (each warp n-block = one head)
    const int nbase = n0 + wn * 64;
    const int which = nbase >> 10;          // 0=q, 1=k, 2=v
    const bool skip_lo = (mode == 0) && (which == 1);

    float c[2][8][4];
#pragma unroll
    for (int mt = 0; mt < 2; mt++)
#pragma unroll
        for (int nt = 0; nt < 8; nt++)
#pragma unroll
            for (int j = 0; j < 4; j++) c[mt][nt][j] = 0.f;

    const int row  = tid >> 1;
    const int half = tid & 1;
    const size_t gA0 = (size_t)(m0 + row) * DM * 2 + half * 16;
    const size_t gB0 = (size_t)(n0 + row) * DM * 2 + half * 16;
    const uint32_t sRow = (uint32_t)(row * GLDB + half * 16);

    auto issue = [&](int ch) {
        const size_t ko = (size_t)ch * 32;
        const uint32_t s = sb + (ch & 3) * F_STAGE + sRow;
        cp16(s + F_AH, (const char*)Ahi + gA0 + ko);
        cp16(s + F_AL, (const char*)Alo + gA0 + ko);
        cp16(s + F_BH, (const char*)Bh + gB0 + ko);
        CP_COMMIT();
    };

    issue(0); issue(1); issue(2);

    for (int ch = 0; ch < 64; ch++) {
        CP_WAIT2();
        __syncthreads();

        const uint32_t sbuf = sb + (ch & 3) * F_STAGE;
        uint32_t ah[2][4], al[2][4];
#pragma unroll
        for (int mt = 0; mt < 2; mt++) {
            const uint32_t abase = sbuf +
                (uint32_t)((wm * 32 + mt * 16 + lrow) * GLDB + lcol * 2);
            ldsm_x4(ah[mt], abase + F_AH);
            if (!skip_lo) ldsm_x4(al[mt], abase + F_AL);
        }
#pragma unroll
        for (int p = 0; p < 4; p++) {
            const uint32_t bbase = sbuf +
                (uint32_t)((wn * 64 + p * 16 + lrow) * GLDB + lcol * 2);
            uint32_t bh[4];
            ldsm_x4(bh, bbase + F_BH);
#pragma unroll
            for (int mt = 0; mt < 2; mt++) {
                mma_fp16(c[mt][2 * p],     ah[mt], bh[0], bh[2]);
                mma_fp16(c[mt][2 * p + 1], ah[mt], bh[1], bh[3]);
            }
            if (!skip_lo) {
#pragma unroll
                for (int mt = 0; mt < 2; mt++) {
                    mma_fp16(c[mt][2 * p],     al[mt], bh[0], bh[2]);
                    mma_fp16(c[mt][2 * p + 1], al[mt], bh[1], bh[3]);
                }
            }
        }
        if (ch + 3 < 64) issue(ch + 3);
    }

    // ---- epilogue ----
    if (mode == 1) {
#pragma unroll
        for (int nt = 0; nt < 8; nt++) {
            const int nb = n0 + wn * 64 + nt * 8 + qd * 2;
#pragma unroll
            for (int mt = 0; mt < 2; mt++) {
#pragma unroll
                for (int rr = 0; rr < 2; rr++) {
                    const int m = m0 + wm * 32 + mt * 16 + r4 + rr * 8;
                    *(float2*)(Cout + (size_t)m * DM + nb) =
                        make_float2(c[mt][nt][rr * 2 + 0], c[mt][nt][rr * 2 + 1]);
                }
            }
        }
        return;
    }

    const int hh = (nbase & 1023) >> 6;     // head (warp-uniform)

    float bia[8][2];
#pragma unroll
    for (int nt = 0; nt < 8; nt++) {
        bia[nt][0] = bias[nbase + nt * 8 + qd * 2];
        bia[nt][1] = bias[nbase + nt * 8 + qd * 2 + 1];
    }

    if (which == 2) {
        // v: emit fp16 hi/lo
#pragma unroll
        for (int mt = 0; mt < 2; mt++) {
#pragma unroll
            for (int rr = 0; rr < 2; rr++) {
                const int m = m0 + wm * 32 + mt * 16 + r4 + rr * 8;
                const int bidx = m >> 11, ntok = m & 2047;
                const size_t rbase = ((size_t)(bidx * H_ + hh) * N_ + ntok) * DH;
#pragma unroll
                for (int nt = 0; nt < 8; nt++) {
                    const int d = nt * 8 + qd * 2;
                    float f0 = c[mt][nt][rr * 2 + 0] + bia[nt][0];
                    float f1 = c[mt][nt][rr * 2 + 1] + bia[nt][1];
                    *(uint32_t*)(g_vh + rbase + d) = pack_f16(f0, f1);
                    *(uint32_t*)(g_vl + rbase + d) = pack_f16(f0 - f16_round(f0),
                                                              f1 - f16_round(f1));
                }
            }
        }
    } else {
        // q or k: fused L2 normalization over the head's 64 cols
        float sc_ = 1.f;
        if (which == 0)
            sc_ = __expf(fminf(lscale[hh], 4.6051702f)) * 1.44269504f;
#pragma unroll
        for (int mt = 0; mt < 2; mt++) {
#pragma unroll
            for (int rr = 0; rr < 2; rr++) {
                const int m = m0 + wm * 32 + mt * 16 + r4 + rr * 8;
                const int bidx = m >> 11, ntok = m & 2047;
                const size_t rbase = ((size_t)(bidx * H_ + hh) * N_ + ntok) * DH;
                float ss = 0.f;
#pragma unroll
                for (int nt = 0; nt < 8; nt++) {
                    float f0 = c[mt][nt][rr * 2 + 0] + bia[nt][0];
                    float f1 = c[mt][nt][rr * 2 + 1] + bia[nt][1];
                    ss += f0 * f0 + f1 * f1;
                }
                ss += __shfl_xor_sync(0xffffffffu, ss, 1);
                ss += __shfl_xor_sync(0xffffffffu, ss, 2);
                const float inv = sc_ / fmaxf(sqrtf(ss), 1e-12f);
#pragma unroll
                for (int nt = 0; nt < 8; nt++) {
                    const int d = nt * 8 + qd * 2;
                    float f0 = (c[mt][nt][rr * 2 + 0] + bia[nt][0]) * inv;
                    float f1 = (c[mt][nt][rr * 2 + 1] + bia[nt][1]) * inv;
                    if (which == 0) {
                        *(uint32_t*)(g_qh + rbase + d) = pack_f16(f0, f1);
                        *(uint32_t*)(g_ql + rbase + d) = pack_f16(f0 - f16_round(f0),
                                                                  f1 - f16_round(f1));
                    } else {
                        *(uint32_t*)(g_kh + rbase + d) = pack_f16(f0, f1);
                    }
                }
            }
        }
    }
}

// ---------------------------------------------------------------------------
// Flash attention, fp16 2-pass mma.sync + ldmatrix, static-max softmax.
// Exponent shift cs-12 keeps p in fp16 NORMAL range (p typ ~2^-2.4, max 2^12)
// — better packed-p precision for the PV MMA.  Softmax shift-invariant.
// QK: qh*k + ql*k (k single fp16).  PV: p*vh + p*vl.
// CTA = 256 thr (8 warps), Q block 128, K tile 64, KV double-buffered.
// ---------------------------------------------------------------------------
#define ALDB 144
#define AS_QH 0
#define AS_QL (AS_QH + 128 * ALDB)
#define AS_KV (AS_QL + 128 * ALDB)            // 36864
#define KV_ARR   (64 * ALDB)                  // 9216
#define KV_STAGE (3 * KV_ARR)                 // 27648
#define KV_KH 0
#define KV_VH (1 * KV_ARR)
#define KV_VL (2 * KV_ARR)
#define AS_TOTAL (AS_KV + 2 * KV_STAGE)       // 92160 B

__global__ __launch_bounds__(256, 2) void attn_mma_kernel(const float* __restrict__ lscale)
{
    extern __shared__ char smem[];
    const uint32_t sb = smem_u32(smem);
    const int tid  = threadIdx.x;
    const int wid  = tid >> 5;
    const int lane = tid & 31;
    const int qd   = lane & 3;
    const int r4   = lane >> 2;
    const int lrow = ((lane >> 3) & 1) * 8 + (lane & 7);
    const int lcol = (lane >> 4) * 8;
    const int bh = blockIdx.y;
    const int b  = bh >> 4;
    const int h  = bh & 15;
    const int q0 = blockIdx.x * 128;

    // shifted static max: p = 2^(s' - (cs-12)) <= 2^12, typically ~2^-2 (normal fp16)
    const float cs = __expf(fminf(lscale[h], 4.6051702f)) * 1.44269504f - 12.0f;

    const size_t rowbase = (size_t)bh * N_ * DH;

    // ---- Q tile (cp.async, once): 128 rows, 2 threads/row ----
    {
        const int r = tid >> 1, hf = tid & 1;
        const size_t off = (rowbase + (size_t)(q0 + r) * DH) * 2 + hf * 64;
        const uint32_t sq = sb + (uint32_t)(r * ALDB + hf * 64);
#pragma unroll
        for (int i = 0; i < 4; i++) {
            cp16(sq + AS_QH + i * 16, (const char*)g_qh + off + i * 16);
            cp16(sq + AS_QL + i * 16, (const char*)g_ql + off + i * 16);
        }
    }
    const int kr = tid >> 2;
    const int kq = (tid & 3) * 32;
    auto issue_kv = [&](int j0, int buf) {
        const size_t off = (rowbase + (size_t)(j0 + kr) * DH) * 2 + kq;
        const uint32_t s = sb + AS_KV + buf * KV_STAGE + (uint32_t)(kr * ALDB + kq);
#pragma unroll
        for (int i = 0; i < 2; i++) {
            cp16(s + KV_KH + i * 16, (const char*)g_kh + off + i * 16);
            cp16(s + KV_VH + i * 16, (const char*)g_vh + off + i * 16);
            cp16(s + KV_VL + i * 16, (const char*)g_vl + off + i * 16);
        }
        CP_COMMIT();
    };
    issue_kv(0, 0);

    float o[8][4];
#pragma unroll
    for (int dn = 0; dn < 8; dn++)
#pragma unroll
        for (int j = 0; j < 4; j++) o[dn][j] = 0.f;
    float lsum0 = 0.f, lsum1 = 0.f;

    for (int t = 0; t < N_ / 64; t++) {
        CP_WAIT0();
        __syncthreads();
        const uint32_t kvb = sb + AS_KV + (t & 1) * KV_STAGE;

        // ---- S = Q K^T (fp16 2-pass) ----
        float s[8][4];
#pragma unroll
        for (int nt = 0; nt < 8; nt++)
#pragma unroll
            for (int j = 0; j < 4; j++) s[nt][j] = 0.f;

#pragma unroll
        for (int ks = 0; ks < 4; ks++) {
            uint32_t aqh[4], aql[4];
            const uint32_t abase = sb +
                (uint32_t)((wid * 16 + lrow) * ALDB + (ks * 16 + lcol) * 2);
            ldsm_x4(aqh, abase + AS_QH);
            ldsm_x4(aql, abase + AS_QL);
#pragma unroll
            for (int p = 0; p < 4; p++) {
                const uint32_t bbase = kvb +
                    (uint32_t)((p * 16 + lrow) * ALDB + (ks * 16 + lcol) * 2);
                uint32_t kh[4];
                ldsm_x4(kh, bbase + KV_KH);
                mma_fp16(s[2 * p],     aqh, kh[0], kh[2]);
                mma_fp16(s[2 * p + 1], aqh, kh[1], kh[3]);
                mma_fp16(s[2 * p],     aql, kh[0], kh[2]);
                mma_fp16(s[2 * p + 1], aql, kh[1], kh[3]);
            }
        }

        // ---- shifted static softmax numerators ----
#pragma unroll
        for (int nt = 0; nt < 8; nt++) {
            s[nt][0] = exp2f(s[nt][0] - cs);
            s[nt][1] = exp2f(s[nt][1] - cs);
            s[nt][2] = exp2f(s[nt][2] - cs);
            s[nt][3] = exp2f(s[nt][3] - cs);
            lsum0 += s[nt][0] + s[nt][1];
            lsum1 += s[nt][2] + s[nt][3];
        }

        // ---- O += P V (fp16 2-pass: p*(vh+vl)) ----
#pragma unroll
        for (int kt = 0; kt < 4; kt++) {
            const int u = 2 * kt, v2 = 2 * kt + 1;
            uint32_t pah[4];
            pah[0] = pack_f16(s[u][0],  s[u][1]);
            pah[1] = pack_f16(s[u][2],  s[u][3]);
            pah[2] = pack_f16(s[v2][0], s[v2][1]);
            pah[3] = pack_f16(s[v2][2], s[v2][3]);
#pragma unroll
            for (int p = 0; p < 4; p++) {
                const uint32_t vbase = kvb +
                    (uint32_t)((kt * 16 + lrow) * ALDB + (p * 16 + lcol) * 2);
                uint32_t vh[4], vl[4];
                ldsm_x4_t(vh, vbase + KV_VH);
                ldsm_x4_t(vl, vbase + KV_VL);
                mma_fp16(o[2 * p],     pah, vh[0], vh[1]);
                mma_fp16(o[2 * p + 1], pah, vh[2], vh[3]);
                mma_fp16(o[2 * p],     pah, vl[0], vl[1]);
                mma_fp16(o[2 * p + 1], pah, vl[2], vl[3]);
            }
        }
        if (t + 1 < N_ / 64) issue_kv((t + 1) * 64, (t + 1) & 1);
    }

    // ---- final row-sum reduction across the quad, then normalize ----
    lsum0 += __shfl_xor_sync(0xffffffffu, lsum0, 1);
    lsum0 += __shfl_xor_sync(0xffffffffu, lsum0, 2);
    lsum1 += __shfl_xor_sync(0xffffffffu, lsum1, 1);
    lsum1 += __shfl_xor_sync(0xffffffffu, lsum1, 2);
    const float inv0 = 1.f / lsum0;
    const float inv1 = 1.f / lsum1;
#pragma unroll
    for (int dn = 0; dn < 8; dn++) {
        const int d = dn * 8 + qd * 2;
#pragma unroll
        for (int rr = 0; rr < 2; rr++) {
            const int n = q0 + wid * 16 + r4 + rr * 8;
            const float inv = rr ? inv1 : inv0;
            const float f0 = o[dn][rr * 2 + 0] * inv;
            const float f1 = o[dn][rr * 2 + 1] * inv;
            const size_t idx = (size_t)(b * N_ + n) * DM + h * 64 + d;
            *(uint32_t*)(g_aoh + idx) = pack_f16(f0, f1);
            *(uint32_t*)(g_aol + idx) = pack_f16(f0 - f16_round(f0), f1 - f16_round(f1));
        }
    }
}

// ---------------------------------------------------------------------------
extern "C" void kernel_launch(void* const* d_in, const int* in_sizes, int n_in,
                              void* d_out, int out_size)
{
    const float* x      = (const float*)d_in[0];
    const float* w_qkv  = (const float*)d_in[1];
    const float* b_qkv  = (const float*)d_in[2];
    const float* w_out  = (const float*)d_in[3];
    const float* lscale = (const float*)d_in[4];
    float* out = (float*)d_out;

    __half *xh, *xl, *wqh, *woh, *aoh, *aol;
    cudaGetSymbolAddress((void**)&xh,  g_x_h);
    cudaGetSymbolAddress((void**)&xl,  g_x_l);
    cudaGetSymbolAddress((void**)&wqh, g_wq_h);
    cudaGetSymbolAddress((void**)&woh, g_wo_h);
    cudaGetSymbolAddress((void**)&aoh, g_aoh);
    cudaGetSymbolAddress((void**)&aol, g_aol);

    cudaFuncSetAttribute(gemm_f16_kernel, cudaFuncAttributeMaxDynamicSharedMemorySize, FS_TOTAL);
    cudaFuncSetAttribute(attn_mma_kernel, cudaFuncAttributeMaxDynamicSharedMemorySize, AS_TOTAL);

    // 0. convert inputs
    decomp_f16_kernel<<<(M_TOT * DM) / 1024, 256>>>(x, xh, xl);
    conv_f16_kernel<<<(QKV_N * DM) / 1024, 256>>>(w_qkv, wqh);
    conv_f16_kernel<<<(DM * DM)    / 1024, 256>>>(w_out, woh);

    // 1. QKV projection (fp16 2-pass; k warps 1-pass) + fused bias+l2norm
    dim3 g1(QKV_N / 128, M_TOT / 128);     // (24, 64)
    gemm_f16_kernel<<<g1, 256, FS_TOTAL>>>(xh, xl, wqh, b_qkv, lscale, nullptr, 0);

    // 2. flash attention (fp16 2-pass, shifted static softmax) -> ao fp16 hi/lo
    dim3 g3(N_ / 128, B_ * H_);            // (16, 64)
    attn_mma_kernel<<<g3, 256, AS_TOTAL>>>(lscale);

    // 3. output projection (fp16 2-pass) -> d_out
    dim3 g4(DM / 128, M_TOT / 128);        // (8, 64)
    gemm_f16_kernel<<<g4, 256, FS_TOTAL>>>(aoh, aol, woh, nullptr, nullptr, out, 1);
}

// round 17
// speedup vs baseline: 1.2735x; 1.1096x over previous
#include <cuda_runtime.h>
#include <cuda_bf16.h>
#include <cuda_fp16.h>
#include <math.h>
#include <stdint.h>

#define B_    4
#define N_    2048
#define H_    16
#define DH    64
#define DM    1024
#define M_TOT (B_ * N_)        // 8192
#define QKV_N (3 * DM)         // 3072
#define NROWS (B_ * H_ * N_)   // 131072

// ---------------------------------------------------------------------------
// Scratch (static device globals — allocation-free per harness rules)
// ---------------------------------------------------------------------------
__device__ __half g_qh[(size_t)NROWS * DH];   // normalized q*scale*log2e, single fp16
__device__ __half g_kh[(size_t)NROWS * DH];   // normalized k, single fp16
__device__ __half g_vh[(size_t)NROWS * DH];   // v fp16 hi
__device__ __half g_vl[(size_t)NROWS * DH];   // v fp16 lo

__device__ __half g_x_h [(size_t)M_TOT * DM]; // x fp16 hi
__device__ __half g_x_l [(size_t)M_TOT * DM]; // x fp16 lo
__device__ __half g_wq_h[(size_t)QKV_N * DM]; // w_qkv single fp16
__device__ __half g_wo_h[(size_t)DM * DM];    // w_out single fp16
__device__ __half g_aoh [(size_t)M_TOT * DM]; // attention out fp16 hi
__device__ __half g_aol [(size_t)M_TOT * DM]; // attention out fp16 lo

// ---------------------------------------------------------------------------
// Helpers
// ---------------------------------------------------------------------------
__device__ __forceinline__ void mma_fp16(float* c, const uint32_t* a,
                                         uint32_t b0, uint32_t b1) {
    asm volatile(
        "mma.sync.aligned.m16n8k16.row.col.f32.f16.f16.f32 "
        "{%0,%1,%2,%3}, {%4,%5,%6,%7}, {%8,%9}, {%0,%1,%2,%3};\n"
        : "+f"(c[0]), "+f"(c[1]), "+f"(c[2]), "+f"(c[3])
        : "r"(a[0]), "r"(a[1]), "r"(a[2]), "r"(a[3]), "r"(b0), "r"(b1));
}
__device__ __forceinline__ uint32_t pack_f16(float x, float y) {
    __half2 t = __floats2half2_rn(x, y);
    return *(uint32_t*)&t;
}
__device__ __forceinline__ float f16_round(float x) {
    return __half2float(__float2half_rn(x));
}
__device__ __forceinline__ uint32_t smem_u32(const void* p) {
    uint32_t a;
    asm("{ .reg .u64 t; cvta.to.shared.u64 t, %1; cvt.u32.u64 %0, t; }" : "=r"(a) : "l"(p));
    return a;
}
__device__ __forceinline__ void cp16(uint32_t dst, const void* src) {
    asm volatile("cp.async.cg.shared.global [%0], [%1], 16;" :: "r"(dst), "l"(src));
}
#define CP_COMMIT() asm volatile("cp.async.commit_group;" ::: "memory")
#define CP_WAIT0()  asm volatile("cp.async.wait_group 0;" ::: "memory")
#define CP_WAIT2()  asm volatile("cp.async.wait_group 2;" ::: "memory")

__device__ __forceinline__ void ldsm_x4(uint32_t* r, uint32_t addr) {
    asm volatile("ldmatrix.sync.aligned.m8n8.x4.shared.b16 {%0,%1,%2,%3}, [%4];"
                 : "=r"(r[0]), "=r"(r[1]), "=r"(r[2]), "=r"(r[3]) : "r"(addr));
}
__device__ __forceinline__ void ldsm_x4_t(uint32_t* r, uint32_t addr) {
    asm volatile("ldmatrix.sync.aligned.m8n8.x4.trans.shared.b16 {%0,%1,%2,%3}, [%4];"
                 : "=r"(r[0]), "=r"(r[1]), "=r"(r[2]), "=r"(r[3]) : "r"(addr));
}

// ---------------------------------------------------------------------------
// f32 -> (fp16 hi, fp16 lo).  4 elems / thread.
// ---------------------------------------------------------------------------
__global__ __launch_bounds__(256) void decomp_f16_kernel(
    const float* __restrict__ src, __half* __restrict__ hi, __half* __restrict__ lo)
{
    size_t i = ((size_t)blockIdx.x * 256 + threadIdx.x) * 4;
    float4 v = *(const float4*)(src + i);
    *(uint32_t*)(hi + i)     = pack_f16(v.x, v.y);
    *(uint32_t*)(hi + i + 2) = pack_f16(v.z, v.w);
    *(uint32_t*)(lo + i)     = pack_f16(v.x - f16_round(v.x), v.y - f16_round(v.y));
    *(uint32_t*)(lo + i + 2) = pack_f16(v.z - f16_round(v.z), v.w - f16_round(v.w));
}

// f32 -> fp16 (single).  4 elems / thread.
__global__ __launch_bounds__(256) void conv_f16_kernel(
    const float* __restrict__ src, __half* __restrict__ dst)
{
    size_t i = ((size_t)blockIdx.x * 256 + threadIdx.x) * 4;
    float4 v = *(const float4*)(src + i);
    *(uint32_t*)(dst + i)     = pack_f16(v.x, v.y);
    *(uint32_t*)(dst + i + 2) = pack_f16(v.z, v.w);
}

// ---------------------------------------------------------------------------
// fp16 GEMM:  C = (Ahi [+ Alo]) @ Bh^T,  B single fp16.
// 4-stage cp.async pipeline, K-chunk 16, ldmatrix frags.
// Block 128x128, 256 thr (8 warps 4x2), warp tile 32x64, 2 CTAs/SM.
// mode 0 (QKV): fused bias+l2norm epilogue; q- AND k-head warps SKIP the
//   Alo pass (both are rounded to single fp16 on output); v keeps 2-pass.
// mode 1: row-major float store to Cout (2-pass).
// ---------------------------------------------------------------------------
#define GLDB  48
#define F_ARR   (128 * GLDB)                // 6144 B
#define F_AH 0
#define F_AL (1 * F_ARR)
#define F_BH (2 * F_ARR)
#define F_STAGE (3 * F_ARR)                 // 18432 B
#define FS_TOTAL (4 * F_STAGE)              // 73728 B

__global__ __launch_bounds__(256, 2) void gemm_f16_kernel(
    const __half* __restrict__ Ahi, const __half* __restrict__ Alo,
    const __half* __restrict__ Bh,
    const float* __restrict__ bias, const float* __restrict__ lscale,
    float* __restrict__ Cout, int mode)
{
    extern __shared__ char smem[];
    const uint32_t sb = smem_u32(smem);
    const int tid  = threadIdx.x;
    const int wid  = tid >> 5;
    const int lane = tid & 31;
    const int wm   = wid & 3;
    const int wn   = wid >> 2;
    const int qd   = lane & 3;
    const int r4   = lane >> 2;
    const int m0 = blockIdx.y * 128;
    const int n0 = blockIdx.x * 128;

    const int lrow = ((lane >> 3) & 1) * 8 + (lane & 7);
    const int lcol = (lane >> 4) * 8;

    // warp-uniform output class for mode 0 (each warp n-block = one head)
    const int nbase = n0 + wn * 64;
    const int which = nbase >> 10;          // 0=q, 1=k, 2=v
    const bool skip_lo = (mode == 0) && (which != 2);

    float c[2][8][4];
#pragma unroll
    for (int mt = 0; mt < 2; mt++)
#pragma unroll
        for (int nt = 0; nt < 8; nt++)
#pragma unroll
            for (int j = 0; j < 4; j++) c[mt][nt][j] = 0.f;

    const int row  = tid >> 1;
    const int half = tid & 1;
    const size_t gA0 = (size_t)(m0 + row) * DM * 2 + half * 16;
    const size_t gB0 = (size_t)(n0 + row) * DM * 2 + half * 16;
    const uint32_t sRow = (uint32_t)(row * GLDB + half * 16);

    auto issue = [&](int ch) {
        const size_t ko = (size_t)ch * 32;
        const uint32_t s = sb + (ch & 3) * F_STAGE + sRow;
        cp16(s + F_AH, (const char*)Ahi + gA0 + ko);
        cp16(s + F_AL, (const char*)Alo + gA0 + ko);
        cp16(s + F_BH, (const char*)Bh + gB0 + ko);
        CP_COMMIT();
    };

    issue(0); issue(1); issue(2);

    for (int ch = 0; ch < 64; ch++) {
        CP_WAIT2();
        __syncthreads();

        const uint32_t sbuf = sb + (ch & 3) * F_STAGE;
        uint32_t ah[2][4], al[2][4];
#pragma unroll
        for (int mt = 0; mt < 2; mt++) {
            const uint32_t abase = sbuf +
                (uint32_t)((wm * 32 + mt * 16 + lrow) * GLDB + lcol * 2);
            ldsm_x4(ah[mt], abase + F_AH);
            if (!skip_lo) ldsm_x4(al[mt], abase + F_AL);
        }
#pragma unroll
        for (int p = 0; p < 4; p++) {
            const uint32_t bbase = sbuf +
                (uint32_t)((wn * 64 + p * 16 + lrow) * GLDB + lcol * 2);
            uint32_t bh[4];
            ldsm_x4(bh, bbase + F_BH);
#pragma unroll
            for (int mt = 0; mt < 2; mt++) {
                mma_fp16(c[mt][2 * p],     ah[mt], bh[0], bh[2]);
                mma_fp16(c[mt][2 * p + 1], ah[mt], bh[1], bh[3]);
            }
            if (!skip_lo) {
#pragma unroll
                for (int mt = 0; mt < 2; mt++) {
                    mma_fp16(c[mt][2 * p],     al[mt], bh[0], bh[2]);
                    mma_fp16(c[mt][2 * p + 1], al[mt], bh[1], bh[3]);
                }
            }
        }
        if (ch + 3 < 64) issue(ch + 3);
    }

    // ---- epilogue ----
    if (mode == 1) {
#pragma unroll
        for (int nt = 0; nt < 8; nt++) {
            const int nb = n0 + wn * 64 + nt * 8 + qd * 2;
#pragma unroll
            for (int mt = 0; mt < 2; mt++) {
#pragma unroll
                for (int rr = 0; rr < 2; rr++) {
                    const int m = m0 + wm * 32 + mt * 16 + r4 + rr * 8;
                    *(float2*)(Cout + (size_t)m * DM + nb) =
                        make_float2(c[mt][nt][rr * 2 + 0], c[mt][nt][rr * 2 + 1]);
                }
            }
        }
        return;
    }

    const int hh = (nbase & 1023) >> 6;     // head (warp-uniform)

    float bia[8][2];
#pragma unroll
    for (int nt = 0; nt < 8; nt++) {
        bia[nt][0] = bias[nbase + nt * 8 + qd * 2];
        bia[nt][1] = bias[nbase + nt * 8 + qd * 2 + 1];
    }

    if (which == 2) {
        // v: emit fp16 hi/lo
#pragma unroll
        for (int mt = 0; mt < 2; mt++) {
#pragma unroll
            for (int rr = 0; rr < 2; rr++) {
                const int m = m0 + wm * 32 + mt * 16 + r4 + rr * 8;
                const int bidx = m >> 11, ntok = m & 2047;
                const size_t rbase = ((size_t)(bidx * H_ + hh) * N_ + ntok) * DH;
#pragma unroll
                for (int nt = 0; nt < 8; nt++) {
                    const int d = nt * 8 + qd * 2;
                    float f0 = c[mt][nt][rr * 2 + 0] + bia[nt][0];
                    float f1 = c[mt][nt][rr * 2 + 1] + bia[nt][1];
                    *(uint32_t*)(g_vh + rbase + d) = pack_f16(f0, f1);
                    *(uint32_t*)(g_vl + rbase + d) = pack_f16(f0 - f16_round(f0),
                                                              f1 - f16_round(f1));
                }
            }
        }
    } else {
        // q or k: fused L2 normalization, emit single fp16
        float sc_ = 1.f;
        if (which == 0)
            sc_ = __expf(fminf(lscale[hh], 4.6051702f)) * 1.44269504f;
        __half* dst = (which == 0) ? g_qh : g_kh;
#pragma unroll
        for (int mt = 0; mt < 2; mt++) {
#pragma unroll
            for (int rr = 0; rr < 2; rr++) {
                const int m = m0 + wm * 32 + mt * 16 + r4 + rr * 8;
                const int bidx = m >> 11, ntok = m & 2047;
                const size_t rbase = ((size_t)(bidx * H_ + hh) * N_ + ntok) * DH;
                float ss = 0.f;
#pragma unroll
                for (int nt = 0; nt < 8; nt++) {
                    float f0 = c[mt][nt][rr * 2 + 0] + bia[nt][0];
                    float f1 = c[mt][nt][rr * 2 + 1] + bia[nt][1];
                    ss += f0 * f0 + f1 * f1;
                }
                ss += __shfl_xor_sync(0xffffffffu, ss, 1);
                ss += __shfl_xor_sync(0xffffffffu, ss, 2);
                const float inv = sc_ / fmaxf(sqrtf(ss), 1e-12f);
#pragma unroll
                for (int nt = 0; nt < 8; nt++) {
                    const int d = nt * 8 + qd * 2;
                    float f0 = (c[mt][nt][rr * 2 + 0] + bia[nt][0]) * inv;
                    float f1 = (c[mt][nt][rr * 2 + 1] + bia[nt][1]) * inv;
                    *(uint32_t*)(dst + rbase + d) = pack_f16(f0, f1);
                }
            }
        }
    }
}

// ---------------------------------------------------------------------------
// Flash attention: QK 1-pass (q single x k single), PV 2-pass (p*(vh+vl)).
// Shifted static softmax keeps p in fp16 normal range.
// CTA = 256 thr (8 warps), Q block 128, K tile 64, KV double-buffered.
// smem: Q 18432 + KV 2 stages x 3 x 9216 = 73728 B -> 2 CTAs/SM.
// ---------------------------------------------------------------------------
#define ALDB 144
#define AS_QH 0
#define AS_KV (AS_QH + 128 * ALDB)            // 18432
#define KV_ARR   (64 * ALDB)                  // 9216
#define KV_STAGE (3 * KV_ARR)                 // 27648
#define KV_KH 0
#define KV_VH (1 * KV_ARR)
#define KV_VL (2 * KV_ARR)
#define AS_TOTAL (AS_KV + 2 * KV_STAGE)       // 73728 B

__global__ __launch_bounds__(256, 2) void attn_mma_kernel(const float* __restrict__ lscale)
{
    extern __shared__ char smem[];
    const uint32_t sb = smem_u32(smem);
    const int tid  = threadIdx.x;
    const int wid  = tid >> 5;
    const int lane = tid & 31;
    const int qd   = lane & 3;
    const int r4   = lane >> 2;
    const int lrow = ((lane >> 3) & 1) * 8 + (lane & 7);
    const int lcol = (lane >> 4) * 8;
    const int bh = blockIdx.y;
    const int b  = bh >> 4;
    const int h  = bh & 15;
    const int q0 = blockIdx.x * 128;

    // shifted static max: p = 2^(s' - (cs-12)) <= 2^12, typically normal fp16
    const float cs = __expf(fminf(lscale[h], 4.6051702f)) * 1.44269504f - 12.0f;

    const size_t rowbase = (size_t)bh * N_ * DH;

    // ---- Q tile (cp.async, once): 128 rows x 128 B, 2 threads/row ----
    {
        const int r = tid >> 1, hf = tid & 1;
        const size_t off = (rowbase + (size_t)(q0 + r) * DH) * 2 + hf * 64;
        const uint32_t sq = sb + (uint32_t)(r * ALDB + hf * 64);
#pragma unroll
        for (int i = 0; i < 4; i++)
            cp16(sq + AS_QH + i * 16, (const char*)g_qh + off + i * 16);
    }
    const int kr = tid >> 2;
    const int kq = (tid & 3) * 32;
    auto issue_kv = [&](int j0, int buf) {
        const size_t off = (rowbase + (size_t)(j0 + kr) * DH) * 2 + kq;
        const uint32_t s = sb + AS_KV + buf * KV_STAGE + (uint32_t)(kr * ALDB + kq);
#pragma unroll
        for (int i = 0; i < 2; i++) {
            cp16(s + KV_KH + i * 16, (const char*)g_kh + off + i * 16);
            cp16(s + KV_VH + i * 16, (const char*)g_vh + off + i * 16);
            cp16(s + KV_VL + i * 16, (const char*)g_vl + off + i * 16);
        }
        CP_COMMIT();
    };
    issue_kv(0, 0);

    float o[8][4];
#pragma unroll
    for (int dn = 0; dn < 8; dn++)
#pragma unroll
        for (int j = 0; j < 4; j++) o[dn][j] = 0.f;
    float lsum0 = 0.f, lsum1 = 0.f;

    for (int t = 0; t < N_ / 64; t++) {
        CP_WAIT0();
        __syncthreads();
        const uint32_t kvb = sb + AS_KV + (t & 1) * KV_STAGE;

        // ---- S = Q K^T (fp16 1-pass) ----
        float s[8][4];
#pragma unroll
        for (int nt = 0; nt < 8; nt++)
#pragma unroll
            for (int j = 0; j < 4; j++) s[nt][j] = 0.f;

#pragma unroll
        for (int ks = 0; ks < 4; ks++) {
            uint32_t aqh[4];
            const uint32_t abase = sb +
                (uint32_t)((wid * 16 + lrow) * ALDB + (ks * 16 + lcol) * 2);
            ldsm_x4(aqh, abase + AS_QH);
#pragma unroll
            for (int p = 0; p < 4; p++) {
                const uint32_t bbase = kvb +
                    (uint32_t)((p * 16 + lrow) * ALDB + (ks * 16 + lcol) * 2);
                uint32_t kh[4];
                ldsm_x4(kh, bbase + KV_KH);
                mma_fp16(s[2 * p],     aqh, kh[0], kh[2]);
                mma_fp16(s[2 * p + 1], aqh, kh[1], kh[3]);
            }
        }

        // ---- shifted static softmax numerators ----
#pragma unroll
        for (int nt = 0; nt < 8; nt++) {
            s[nt][0] = exp2f(s[nt][0] - cs);
            s[nt][1] = exp2f(s[nt][1] - cs);
            s[nt][2] = exp2f(s[nt][2] - cs);
            s[nt][3] = exp2f(s[nt][3] - cs);
            lsum0 += s[nt][0] + s[nt][1];
            lsum1 += s[nt][2] + s[nt][3];
        }

        // ---- O += P V (fp16 2-pass: p*(vh+vl)) ----
#pragma unroll
        for (int kt = 0; kt < 4; kt++) {
            const int u = 2 * kt, v2 = 2 * kt + 1;
            uint32_t pah[4];
            pah[0] = pack_f16(s[u][0],  s[u][1]);
            pah[1] = pack_f16(s[u][2],  s[u][3]);
            pah[2] = pack_f16(s[v2][0], s[v2][1]);
            pah[3] = pack_f16(s[v2][2], s[v2][3]);
#pragma unroll
            for (int p = 0; p < 4; p++) {
                const uint32_t vbase = kvb +
                    (uint32_t)((kt * 16 + lrow) * ALDB + (p * 16 + lcol) * 2);
                uint32_t vh[4], vl[4];
                ldsm_x4_t(vh, vbase + KV_VH);
                ldsm_x4_t(vl, vbase + KV_VL);
                mma_fp16(o[2 * p],     pah, vh[0], vh[1]);
                mma_fp16(o[2 * p + 1], pah, vh[2], vh[3]);
                mma_fp16(o[2 * p],     pah, vl[0], vl[1]);
                mma_fp16(o[2 * p + 1], pah, vl[2], vl[3]);
            }
        }
        if (t + 1 < N_ / 64) issue_kv((t + 1) * 64, (t + 1) & 1);
    }

    // ---- final row-sum reduction across the quad, then normalize ----
    lsum0 += __shfl_xor_sync(0xffffffffu, lsum0, 1);
    lsum0 += __shfl_xor_sync(0xffffffffu, lsum0, 2);
    lsum1 += __shfl_xor_sync(0xffffffffu, lsum1, 1);
    lsum1 += __shfl_xor_sync(0xffffffffu, lsum1, 2);
    const float inv0 = 1.f / lsum0;
    const float inv1 = 1.f / lsum1;
#pragma unroll
    for (int dn = 0; dn < 8; dn++) {
        const int d = dn * 8 + qd * 2;
#pragma unroll
        for (int rr = 0; rr < 2; rr++) {
            const int n = q0 + wid * 16 + r4 + rr * 8;
            const float inv = rr ? inv1 : inv0;
            const float f0 = o[dn][rr * 2 + 0] * inv;
            const float f1 = o[dn][rr * 2 + 1] * inv;
            const size_t idx = (size_t)(b * N_ + n) * DM + h * 64 + d;
            *(uint32_t*)(g_aoh + idx) = pack_f16(f0, f1);
            *(uint32_t*)(g_aol + idx) = pack_f16(f0 - f16_round(f0), f1 - f16_round(f1));
        }
    }
}

// ---------------------------------------------------------------------------
extern "C" void kernel_launch(void* const* d_in, const int* in_sizes, int n_in,
                              void* d_out, int out_size)
{
    const float* x      = (const float*)d_in[0];
    const float* w_qkv  = (const float*)d_in[1];
    const float* b_qkv  = (const float*)d_in[2];
    const float* w_out  = (const float*)d_in[3];
    const float* lscale = (const float*)d_in[4];
    float* out = (float*)d_out;

    __half *xh, *xl, *wqh, *woh, *aoh, *aol;
    cudaGetSymbolAddress((void**)&xh,  g_x_h);
    cudaGetSymbolAddress((void**)&xl,  g_x_l);
    cudaGetSymbolAddress((void**)&wqh, g_wq_h);
    cudaGetSymbolAddress((void**)&woh, g_wo_h);
    cudaGetSymbolAddress((void**)&aoh, g_aoh);
    cudaGetSymbolAddress((void**)&aol, g_aol);

    cudaFuncSetAttribute(gemm_f16_kernel, cudaFuncAttributeMaxDynamicSharedMemorySize, FS_TOTAL);
    cudaFuncSetAttribute(attn_mma_kernel, cudaFuncAttributeMaxDynamicSharedMemorySize, AS_TOTAL);

    // 0. convert inputs
    decomp_f16_kernel<<<(M_TOT * DM) / 1024, 256>>>(x, xh, xl);
    conv_f16_kernel<<<(QKV_N * DM) / 1024, 256>>>(w_qkv, wqh);
    conv_f16_kernel<<<(DM * DM)    / 1024, 256>>>(w_out, woh);

    // 1. QKV projection (q,k warps 1-pass; v 2-pass) + fused bias+l2norm
    dim3 g1(QKV_N / 128, M_TOT / 128);     // (24, 64)
    gemm_f16_kernel<<<g1, 256, FS_TOTAL>>>(xh, xl, wqh, b_qkv, lscale, nullptr, 0);

    // 2. flash attention (QK 1-pass, PV 2-pass) -> ao fp16 hi/lo
    dim3 g3(N_ / 128, B_ * H_);            // (16, 64)
    attn_mma_kernel<<<g3, 256, AS_TOTAL>>>(lscale);

    // 3. output projection (fp16 2-pass) -> d_out
    dim3 g4(DM / 128, M_TOT / 128);        // (8, 64)
    gemm_f16_kernel<<<g4, 256, FS_TOTAL>>>(aoh, aol, woh, nullptr, nullptr, out, 1);
}